// round 1
// baseline (speedup 1.0000x reference)
#include <cuda_runtime.h>

#define BATCH 4096
#define LAYERS 4
#define EMB 128
#define FEAT 256
#define NEIGH 32
#define PAIRS (BATCH*LAYERS)   // 16384

// Scratch (device globals: allocation-free rule)
__device__ float g_sumfeat[PAIRS * FEAT];   // 16 MB
__device__ float g_h[PAIRS * EMB];          // 8 MB
__device__ float g_scores[PAIRS];

// ---------------------------------------------------------------------------
// K1: neighbor gather + sum over 32 neighbors.
// pair p = b*4 + l (natural layout of neighs_i [B,L,J]).
// sumfeat[p][f] = sum_j features[neighs[p*32+j]][f]
// Block: 16 pairs, 256 threads. thread -> (group g = pair slot, f4 = float4 col)
// ---------------------------------------------------------------------------
__global__ __launch_bounds__(256) void k1_gather(const int* __restrict__ neighs,
                                                 const float* __restrict__ feats) {
    __shared__ int idxs[16 * 32];
    const int tid = threadIdx.x;
    const int pbase = blockIdx.x * 16;
    idxs[tid]       = neighs[pbase * 32 + tid];
    idxs[tid + 256] = neighs[pbase * 32 + tid + 256];
    __syncthreads();

    const int g  = tid >> 6;    // 0..3
    const int f4 = tid & 63;    // float4 column 0..63
    const float4* __restrict__ feats4 = (const float4*)feats;

    #pragma unroll
    for (int it = 0; it < 4; it++) {
        const int pl = it * 4 + g;                 // local pair 0..15
        float4 a0 = make_float4(0.f, 0.f, 0.f, 0.f);
        float4 a1 = make_float4(0.f, 0.f, 0.f, 0.f);
        #pragma unroll
        for (int j = 0; j < NEIGH; j += 2) {
            const int n0 = idxs[pl * 32 + j];
            const int n1 = idxs[pl * 32 + j + 1];
            const float4 v0 = feats4[n0 * 64 + f4];
            const float4 v1 = feats4[n1 * 64 + f4];
            a0.x += v0.x; a0.y += v0.y; a0.z += v0.z; a0.w += v0.w;
            a1.x += v1.x; a1.y += v1.y; a1.z += v1.z; a1.w += v1.w;
        }
        float4 o;
        o.x = a0.x + a1.x; o.y = a0.y + a1.y; o.z = a0.z + a1.z; o.w = a0.w + a1.w;
        ((float4*)g_sumfeat)[(pbase + pl) * 64 + f4] = o;
    }
}

// ---------------------------------------------------------------------------
// K2: per-layer GEMM  h[b,l,:] = sumfeat[b,l,:] @ W_l   ([4096,256]@[256,128])
// grid = (32, 4): 128-row tiles x layer. 256 thr, 8x8 register tile, BK=32.
// ---------------------------------------------------------------------------
__global__ __launch_bounds__(256) void k2_gemm(const float* __restrict__ W) {
    const int l  = blockIdx.y;
    const int bm = blockIdx.x;
    __shared__ float As[32][132];   // transposed A tile, padded (16B-aligned rows)
    __shared__ float Bs[32][128];

    const int tid = threadIdx.x;
    const int tr = tid >> 4;   // 0..15
    const int tc = tid & 15;   // 0..15

    float acc[8][8];
    #pragma unroll
    for (int i = 0; i < 8; i++)
        #pragma unroll
        for (int j = 0; j < 8; j++) acc[i][j] = 0.f;

    const float* __restrict__ Wl = W + l * FEAT * EMB;

    for (int k0 = 0; k0 < FEAT; k0 += 32) {
        #pragma unroll
        for (int i = 0; i < 16; i++) {
            const int idx = tid + i * 256;
            const int row = idx >> 5, kk = idx & 31;
            As[kk][row] = g_sumfeat[((bm * 128 + row) * 4 + l) * FEAT + k0 + kk];
        }
        #pragma unroll
        for (int i = 0; i < 16; i++) {
            const int idx = tid + i * 256;
            const int f = idx >> 7, m = idx & 127;
            Bs[f][m] = Wl[(k0 + f) * EMB + m];
        }
        __syncthreads();
        #pragma unroll
        for (int kk = 0; kk < 32; kk++) {
            const float4 av0 = *(const float4*)&As[kk][tr * 8];
            const float4 av1 = *(const float4*)&As[kk][tr * 8 + 4];
            const float4 bv0 = *(const float4*)&Bs[kk][tc * 8];
            const float4 bv1 = *(const float4*)&Bs[kk][tc * 8 + 4];
            const float a[8] = {av0.x, av0.y, av0.z, av0.w, av1.x, av1.y, av1.z, av1.w};
            const float b[8] = {bv0.x, bv0.y, bv0.z, bv0.w, bv1.x, bv1.y, bv1.z, bv1.w};
            #pragma unroll
            for (int i = 0; i < 8; i++)
                #pragma unroll
                for (int j = 0; j < 8; j++) acc[i][j] = fmaf(a[i], b[j], acc[i][j]);
        }
        __syncthreads();
    }
    #pragma unroll
    for (int i = 0; i < 8; i++) {
        const int row = bm * 128 + tr * 8 + i;
        float4* dst = (float4*)&g_h[(row * 4 + l) * EMB + tc * 8];
        dst[0] = make_float4(acc[i][0], acc[i][1], acc[i][2], acc[i][3]);
        dst[1] = make_float4(acc[i][4], acc[i][5], acc[i][6], acc[i][7]);
    }
}

// ---------------------------------------------------------------------------
// K3: scores[p] = tanh(H[p,:] @ Ws1) . Ws2    ([16384,128]@[128,128] fused)
// grid = 128 (128-row tiles). Same 8x8 GEMM core; tanh+Ws2 reduce in epilogue.
// ---------------------------------------------------------------------------
__global__ __launch_bounds__(256) void k3_scores(const float* __restrict__ Ws1,
                                                 const float* __restrict__ Ws2) {
    __shared__ float As[32][132];
    __shared__ float Bs[32][128];
    __shared__ float red[128][16];
    __shared__ float w2s[128];

    const int tid = threadIdx.x;
    if (tid < 128) w2s[tid] = Ws2[tid];
    const int tr = tid >> 4, tc = tid & 15;
    const int bm = blockIdx.x;

    float acc[8][8];
    #pragma unroll
    for (int i = 0; i < 8; i++)
        #pragma unroll
        for (int j = 0; j < 8; j++) acc[i][j] = 0.f;

    for (int k0 = 0; k0 < EMB; k0 += 32) {
        #pragma unroll
        for (int i = 0; i < 16; i++) {
            const int idx = tid + i * 256;
            const int row = idx >> 5, kk = idx & 31;
            As[kk][row] = g_h[(bm * 128 + row) * EMB + k0 + kk];
        }
        #pragma unroll
        for (int i = 0; i < 16; i++) {
            const int idx = tid + i * 256;
            const int f = idx >> 7, m = idx & 127;
            Bs[f][m] = Ws1[(k0 + f) * EMB + m];
        }
        __syncthreads();
        #pragma unroll
        for (int kk = 0; kk < 32; kk++) {
            const float4 av0 = *(const float4*)&As[kk][tr * 8];
            const float4 av1 = *(const float4*)&As[kk][tr * 8 + 4];
            const float4 bv0 = *(const float4*)&Bs[kk][tc * 8];
            const float4 bv1 = *(const float4*)&Bs[kk][tc * 8 + 4];
            const float a[8] = {av0.x, av0.y, av0.z, av0.w, av1.x, av1.y, av1.z, av1.w};
            const float b[8] = {bv0.x, bv0.y, bv0.z, bv0.w, bv1.x, bv1.y, bv1.z, bv1.w};
            #pragma unroll
            for (int i = 0; i < 8; i++)
                #pragma unroll
                for (int j = 0; j < 8; j++) acc[i][j] = fmaf(a[i], b[j], acc[i][j]);
        }
        __syncthreads();
    }
    // epilogue: tanh, dot with Ws2, reduce across the 16 column-threads
    #pragma unroll
    for (int i = 0; i < 8; i++) {
        float p = 0.f;
        #pragma unroll
        for (int j = 0; j < 8; j++) p = fmaf(tanhf(acc[i][j]), w2s[tc * 8 + j], p);
        red[tr * 8 + i][tc] = p;
    }
    __syncthreads();
    if (tid < 128) {
        float s = 0.f;
        #pragma unroll
        for (int c = 0; c < 16; c++) s += red[tid][c];
        g_scores[bm * 128 + tid] = s;
    }
}

// ---------------------------------------------------------------------------
// K4: softmax over layers, attention-weighted agg, agg@TW (32-b batched, TW
// amortized in registers), residual layer_embs gather, L2 normalize.
// grid = 128 blocks x 128 threads; block handles 32 batch rows.
// ---------------------------------------------------------------------------
__global__ __launch_bounds__(128) void k4_final(const float* __restrict__ TW,
                                                const float* __restrict__ lemb,
                                                const int* __restrict__ node_i,
                                                const int* __restrict__ layers,
                                                float* __restrict__ out) {
    __shared__ float att_s[32][4];
    __shared__ float aggs[32][128];
    __shared__ float red[4];

    const int tid = threadIdx.x;   // = m
    const int B0 = blockIdx.x * 32;

    if (tid < 32) {
        const int base = (B0 + tid) * 4;
        const float s0 = g_scores[base + 0];
        const float s1 = g_scores[base + 1];
        const float s2 = g_scores[base + 2];
        const float s3 = g_scores[base + 3];
        const float mx = fmaxf(fmaxf(s0, s1), fmaxf(s2, s3));
        const float e0 = __expf(s0 - mx), e1 = __expf(s1 - mx);
        const float e2 = __expf(s2 - mx), e3 = __expf(s3 - mx);
        const float inv = 1.f / (e0 + e1 + e2 + e3);
        att_s[tid][0] = e0 * inv; att_s[tid][1] = e1 * inv;
        att_s[tid][2] = e2 * inv; att_s[tid][3] = e3 * inv;
    }
    __syncthreads();

    const int m = tid;
    for (int b = 0; b < 32; b++) {
        const int base = (B0 + b) * 4;
        float a = 0.f;
        #pragma unroll
        for (int l = 0; l < 4; l++)
            a = fmaf(att_s[b][l], g_h[(base + l) * EMB + m], a);
        aggs[b][m] = a;
    }
    __syncthreads();

    float ne[32];
    #pragma unroll
    for (int b = 0; b < 32; b++) ne[b] = 0.f;

    for (int k = 0; k < EMB; k += 4) {
        const float w0 = TW[(k + 0) * EMB + m];
        const float w1 = TW[(k + 1) * EMB + m];
        const float w2 = TW[(k + 2) * EMB + m];
        const float w3 = TW[(k + 3) * EMB + m];
        #pragma unroll
        for (int b = 0; b < 32; b++) {
            const float4 s = *(const float4*)&aggs[b][k];
            ne[b] = fmaf(s.x, w0, fmaf(s.y, w1, fmaf(s.z, w2, fmaf(s.w, w3, ne[b]))));
        }
    }

    const int lane = tid & 31, wrp = tid >> 5;
    #pragma unroll
    for (int b = 0; b < 32; b++) {
        const int bg = B0 + b;
        const float f = ne[b] + lemb[(node_i[bg] * 4 + layers[bg]) * EMB + m];
        float v = f * f;
        #pragma unroll
        for (int off = 16; off > 0; off >>= 1)
            v += __shfl_xor_sync(0xffffffffu, v, off);
        if (lane == 0) red[wrp] = v;
        __syncthreads();
        const float nrm = sqrtf(red[0] + red[1] + red[2] + red[3]);
        out[bg * EMB + m] = f / fmaxf(nrm, 1e-12f);
        __syncthreads();
    }
}

// ---------------------------------------------------------------------------
// Inputs (metadata order = setup_inputs order):
// 0 layers[4096] i32, 1 node_i[4096] i32, 2 neighs_i[4096*4*32] i32,
// 3 features[100000*256] f32, 4 layer_embs[100000*4*128] f32,
// 5 neigh_emb_trans[4*256*128] f32, 6 trans_weights[128*128] f32,
// 7 trans_weights_s1[128*128] f32, 8 trans_weights_s2[128] f32
// out: [4096,128] f32
// ---------------------------------------------------------------------------
extern "C" void kernel_launch(void* const* d_in, const int* in_sizes, int n_in,
                              void* d_out, int out_size) {
    const int*   layers  = (const int*)d_in[0];
    const int*   node_i  = (const int*)d_in[1];
    const int*   neighs  = (const int*)d_in[2];
    const float* feats   = (const float*)d_in[3];
    const float* lemb    = (const float*)d_in[4];
    const float* net     = (const float*)d_in[5];
    const float* TW      = (const float*)d_in[6];
    const float* Ws1     = (const float*)d_in[7];
    const float* Ws2     = (const float*)d_in[8];
    float* out = (float*)d_out;

    k1_gather<<<PAIRS / 16, 256>>>(neighs, feats);
    k2_gemm<<<dim3(BATCH / 128, LAYERS), 256>>>(net);
    k3_scores<<<PAIRS / 128, 256>>>(Ws1, Ws2);
    k4_final<<<BATCH / 32, 128>>>(TW, lemb, node_i, layers, out);
}

// round 2
// speedup vs baseline: 1.1642x; 1.1642x over previous
#include <cuda_runtime.h>

#define BATCH 4096
#define LAYERS 4
#define EMB 128
#define FEAT 256
#define NEIGH 32
#define PAIRS (BATCH*LAYERS)   // 16384

// Scratch (device globals: allocation-free rule)
__device__ float g_sumfeat[PAIRS * FEAT];   // 16 MB
__device__ float g_h[PAIRS * EMB];          // 8 MB
__device__ float g_scores[PAIRS];

// ---------------------------------------------------------------------------
// K1: neighbor gather + sum over 32 neighbors.
// ---------------------------------------------------------------------------
__global__ __launch_bounds__(256) void k1_gather(const int* __restrict__ neighs,
                                                 const float* __restrict__ feats) {
    __shared__ int idxs[16 * 32];
    const int tid = threadIdx.x;
    const int pbase = blockIdx.x * 16;
    idxs[tid]       = neighs[pbase * 32 + tid];
    idxs[tid + 256] = neighs[pbase * 32 + tid + 256];
    __syncthreads();

    const int g  = tid >> 6;    // 0..3
    const int f4 = tid & 63;    // float4 column 0..63
    const float4* __restrict__ feats4 = (const float4*)feats;

    #pragma unroll
    for (int it = 0; it < 4; it++) {
        const int pl = it * 4 + g;                 // local pair 0..15
        float4 a0 = make_float4(0.f, 0.f, 0.f, 0.f);
        float4 a1 = make_float4(0.f, 0.f, 0.f, 0.f);
        #pragma unroll
        for (int j = 0; j < NEIGH; j += 2) {
            const int n0 = idxs[pl * 32 + j];
            const int n1 = idxs[pl * 32 + j + 1];
            const float4 v0 = feats4[n0 * 64 + f4];
            const float4 v1 = feats4[n1 * 64 + f4];
            a0.x += v0.x; a0.y += v0.y; a0.z += v0.z; a0.w += v0.w;
            a1.x += v1.x; a1.y += v1.y; a1.z += v1.z; a1.w += v1.w;
        }
        float4 o;
        o.x = a0.x + a1.x; o.y = a0.y + a1.y; o.z = a0.z + a1.z; o.w = a0.w + a1.w;
        ((float4*)g_sumfeat)[(pbase + pl) * 64 + f4] = o;
    }
}

// ---------------------------------------------------------------------------
// K2: per-layer GEMM  h[b,l,:] = sumfeat[b,l,:] @ W_l   ([4096,256]@[256,128])
// ---------------------------------------------------------------------------
__global__ __launch_bounds__(256) void k2_gemm(const float* __restrict__ W) {
    const int l  = blockIdx.y;
    const int bm = blockIdx.x;
    __shared__ float As[32][132];
    __shared__ float Bs[32][128];

    const int tid = threadIdx.x;
    const int tr = tid >> 4;   // 0..15
    const int tc = tid & 15;   // 0..15

    float acc[8][8];
    #pragma unroll
    for (int i = 0; i < 8; i++)
        #pragma unroll
        for (int j = 0; j < 8; j++) acc[i][j] = 0.f;

    const float* __restrict__ Wl = W + l * FEAT * EMB;

    for (int k0 = 0; k0 < FEAT; k0 += 32) {
        #pragma unroll
        for (int i = 0; i < 16; i++) {
            const int idx = tid + i * 256;
            const int row = idx >> 5, kk = idx & 31;
            As[kk][row] = g_sumfeat[((bm * 128 + row) * 4 + l) * FEAT + k0 + kk];
        }
        #pragma unroll
        for (int i = 0; i < 16; i++) {
            const int idx = tid + i * 256;
            const int f = idx >> 7, m = idx & 127;
            Bs[f][m] = Wl[(k0 + f) * EMB + m];
        }
        __syncthreads();
        #pragma unroll
        for (int kk = 0; kk < 32; kk++) {
            const float4 av0 = *(const float4*)&As[kk][tr * 8];
            const float4 av1 = *(const float4*)&As[kk][tr * 8 + 4];
            const float4 bv0 = *(const float4*)&Bs[kk][tc * 8];
            const float4 bv1 = *(const float4*)&Bs[kk][tc * 8 + 4];
            const float a[8] = {av0.x, av0.y, av0.z, av0.w, av1.x, av1.y, av1.z, av1.w};
            const float b[8] = {bv0.x, bv0.y, bv0.z, bv0.w, bv1.x, bv1.y, bv1.z, bv1.w};
            #pragma unroll
            for (int i = 0; i < 8; i++)
                #pragma unroll
                for (int j = 0; j < 8; j++) acc[i][j] = fmaf(a[i], b[j], acc[i][j]);
        }
        __syncthreads();
    }
    #pragma unroll
    for (int i = 0; i < 8; i++) {
        const int row = bm * 128 + tr * 8 + i;
        float4* dst = (float4*)&g_h[(row * 4 + l) * EMB + tc * 8];
        dst[0] = make_float4(acc[i][0], acc[i][1], acc[i][2], acc[i][3]);
        dst[1] = make_float4(acc[i][4], acc[i][5], acc[i][6], acc[i][7]);
    }
}

// ---------------------------------------------------------------------------
// K3: scores[p] = tanh(H[p,:] @ Ws1) . Ws2
// ---------------------------------------------------------------------------
__global__ __launch_bounds__(256) void k3_scores(const float* __restrict__ Ws1,
                                                 const float* __restrict__ Ws2) {
    __shared__ float As[32][132];
    __shared__ float Bs[32][128];
    __shared__ float red[128][16];
    __shared__ float w2s[128];

    const int tid = threadIdx.x;
    if (tid < 128) w2s[tid] = Ws2[tid];
    const int tr = tid >> 4, tc = tid & 15;
    const int bm = blockIdx.x;

    float acc[8][8];
    #pragma unroll
    for (int i = 0; i < 8; i++)
        #pragma unroll
        for (int j = 0; j < 8; j++) acc[i][j] = 0.f;

    for (int k0 = 0; k0 < EMB; k0 += 32) {
        #pragma unroll
        for (int i = 0; i < 16; i++) {
            const int idx = tid + i * 256;
            const int row = idx >> 5, kk = idx & 31;
            As[kk][row] = g_h[(bm * 128 + row) * EMB + k0 + kk];
        }
        #pragma unroll
        for (int i = 0; i < 16; i++) {
            const int idx = tid + i * 256;
            const int f = idx >> 7, m = idx & 127;
            Bs[f][m] = Ws1[(k0 + f) * EMB + m];
        }
        __syncthreads();
        #pragma unroll
        for (int kk = 0; kk < 32; kk++) {
            const float4 av0 = *(const float4*)&As[kk][tr * 8];
            const float4 av1 = *(const float4*)&As[kk][tr * 8 + 4];
            const float4 bv0 = *(const float4*)&Bs[kk][tc * 8];
            const float4 bv1 = *(const float4*)&Bs[kk][tc * 8 + 4];
            const float a[8] = {av0.x, av0.y, av0.z, av0.w, av1.x, av1.y, av1.z, av1.w};
            const float b[8] = {bv0.x, bv0.y, bv0.z, bv0.w, bv1.x, bv1.y, bv1.z, bv1.w};
            #pragma unroll
            for (int i = 0; i < 8; i++)
                #pragma unroll
                for (int j = 0; j < 8; j++) acc[i][j] = fmaf(a[i], b[j], acc[i][j]);
        }
        __syncthreads();
    }
    #pragma unroll
    for (int i = 0; i < 8; i++) {
        float p = 0.f;
        #pragma unroll
        for (int j = 0; j < 8; j++) p = fmaf(tanhf(acc[i][j]), w2s[tc * 8 + j], p);
        red[tr * 8 + i][tc] = p;
    }
    __syncthreads();
    if (tid < 128) {
        float s = 0.f;
        #pragma unroll
        for (int c = 0; c < 16; c++) s += red[tid][c];
        g_scores[bm * 128 + tid] = s;
    }
}

// ---------------------------------------------------------------------------
// K4 (rewritten): softmax + agg + agg@TW + residual + L2 normalize.
// grid = 512 blocks x 128 threads; each block handles 8 batch rows.
// 4x more CTAs than before, 4x shorter serial row loop, same TW amortization
// (TW re-read 512x = 32MB of L2 traffic, ~3us).
// ---------------------------------------------------------------------------
__global__ __launch_bounds__(128) void k4_final(const float* __restrict__ TW,
                                                const float* __restrict__ lemb,
                                                const int* __restrict__ node_i,
                                                const int* __restrict__ layers,
                                                float* __restrict__ out) {
    __shared__ float att_s[8][4];
    __shared__ float aggs[8][128];
    __shared__ float red[4];

    const int tid = threadIdx.x;   // = m (0..127)
    const int B0 = blockIdx.x * 8;

    // softmax over 4 layers, one thread per row
    if (tid < 8) {
        const int base = (B0 + tid) * 4;
        const float s0 = g_scores[base + 0];
        const float s1 = g_scores[base + 1];
        const float s2 = g_scores[base + 2];
        const float s3 = g_scores[base + 3];
        const float mx = fmaxf(fmaxf(s0, s1), fmaxf(s2, s3));
        const float e0 = __expf(s0 - mx), e1 = __expf(s1 - mx);
        const float e2 = __expf(s2 - mx), e3 = __expf(s3 - mx);
        const float inv = 1.f / (e0 + e1 + e2 + e3);
        att_s[tid][0] = e0 * inv; att_s[tid][1] = e1 * inv;
        att_s[tid][2] = e2 * inv; att_s[tid][3] = e3 * inv;
    }
    __syncthreads();

    // attention-weighted aggregation -> aggs[8][128]
    const int m = tid;
    #pragma unroll
    for (int b = 0; b < 8; b++) {
        const int base = (B0 + b) * 4;
        float a = 0.f;
        #pragma unroll
        for (int l = 0; l < 4; l++)
            a = fmaf(att_s[b][l], g_h[(base + l) * EMB + m], a);
        aggs[b][m] = a;
    }
    __syncthreads();

    // ne[b][m] = aggs[b][:] @ TW[:, m]  (TW column values live in registers,
    // amortized over the 8 rows)
    float ne[8];
    #pragma unroll
    for (int b = 0; b < 8; b++) ne[b] = 0.f;

    for (int k = 0; k < EMB; k += 4) {
        const float w0 = TW[(k + 0) * EMB + m];
        const float w1 = TW[(k + 1) * EMB + m];
        const float w2 = TW[(k + 2) * EMB + m];
        const float w3 = TW[(k + 3) * EMB + m];
        #pragma unroll
        for (int b = 0; b < 8; b++) {
            const float4 s = *(const float4*)&aggs[b][k];
            ne[b] = fmaf(s.x, w0, fmaf(s.y, w1, fmaf(s.z, w2, fmaf(s.w, w3, ne[b]))));
        }
    }

    // residual + L2 normalize, 8 rows
    const int lane = tid & 31, wrp = tid >> 5;
    #pragma unroll
    for (int b = 0; b < 8; b++) {
        const int bg = B0 + b;
        const float f = ne[b] + lemb[(node_i[bg] * 4 + layers[bg]) * EMB + m];
        float v = f * f;
        #pragma unroll
        for (int off = 16; off > 0; off >>= 1)
            v += __shfl_xor_sync(0xffffffffu, v, off);
        if (lane == 0) red[wrp] = v;
        __syncthreads();
        const float nrm = sqrtf(red[0] + red[1] + red[2] + red[3]);
        out[bg * EMB + m] = f / fmaxf(nrm, 1e-12f);
        __syncthreads();
    }
}

// ---------------------------------------------------------------------------
extern "C" void kernel_launch(void* const* d_in, const int* in_sizes, int n_in,
                              void* d_out, int out_size) {
    const int*   layers  = (const int*)d_in[0];
    const int*   node_i  = (const int*)d_in[1];
    const int*   neighs  = (const int*)d_in[2];
    const float* feats   = (const float*)d_in[3];
    const float* lemb    = (const float*)d_in[4];
    const float* net     = (const float*)d_in[5];
    const float* TW      = (const float*)d_in[6];
    const float* Ws1     = (const float*)d_in[7];
    const float* Ws2     = (const float*)d_in[8];
    float* out = (float*)d_out;

    k1_gather<<<PAIRS / 16, 256>>>(neighs, feats);
    k2_gemm<<<dim3(BATCH / 128, LAYERS), 256>>>(net);
    k3_scores<<<PAIRS / 128, 256>>>(Ws1, Ws2);
    k4_final<<<BATCH / 8, 128>>>(TW, lemb, node_i, layers, out);
}

// round 4
// speedup vs baseline: 1.3428x; 1.1534x over previous
#include <cuda_runtime.h>

#define BATCH 4096
#define LAYERS 4
#define EMB 128
#define FEAT 256
#define NEIGH 32
#define PAIRS (BATCH*LAYERS)   // 16384

typedef unsigned long long u64;

// packed fp32x2 helpers (sm_103a FFMA2 — PTX-only per SASS_QUICKREF)
__device__ __forceinline__ u64 pack2(float x) {
    u64 r; asm("mov.b64 %0,{%1,%1};" : "=l"(r) : "f"(x)); return r;
}
__device__ __forceinline__ u64 fma2(u64 a, u64 b, u64 c) {
    u64 d; asm("fma.rn.f32x2 %0,%1,%2,%3;" : "=l"(d) : "l"(a), "l"(b), "l"(c)); return d;
}
__device__ __forceinline__ float2 unpk(u64 v) {
    float lo, hi; asm("mov.b64 {%0,%1},%2;" : "=f"(lo), "=f"(hi) : "l"(v));
    return make_float2(lo, hi);
}

// Scratch (device globals: allocation-free rule)
__device__ float g_sumfeat[PAIRS * FEAT];   // 16 MB
__device__ float g_h[PAIRS * EMB];          // 8 MB

// ---------------------------------------------------------------------------
// K1: neighbor gather + sum over 32 neighbors. (L2-bandwidth-bound, ~roofline)
// ---------------------------------------------------------------------------
__global__ __launch_bounds__(256) void k1_gather(const int* __restrict__ neighs,
                                                 const float* __restrict__ feats) {
    __shared__ int idxs[16 * 32];
    const int tid = threadIdx.x;
    const int pbase = blockIdx.x * 16;
    idxs[tid]       = neighs[pbase * 32 + tid];
    idxs[tid + 256] = neighs[pbase * 32 + tid + 256];
    __syncthreads();

    const int g  = tid >> 6;
    const int f4 = tid & 63;
    const float4* __restrict__ feats4 = (const float4*)feats;

    #pragma unroll
    for (int it = 0; it < 4; it++) {
        const int pl = it * 4 + g;
        float4 a0 = make_float4(0.f, 0.f, 0.f, 0.f);
        float4 a1 = make_float4(0.f, 0.f, 0.f, 0.f);
        #pragma unroll
        for (int j = 0; j < NEIGH; j += 2) {
            const int n0 = idxs[pl * 32 + j];
            const int n1 = idxs[pl * 32 + j + 1];
            const float4 v0 = feats4[n0 * 64 + f4];
            const float4 v1 = feats4[n1 * 64 + f4];
            a0.x += v0.x; a0.y += v0.y; a0.z += v0.z; a0.w += v0.w;
            a1.x += v1.x; a1.y += v1.y; a1.z += v1.z; a1.w += v1.w;
        }
        float4 o;
        o.x = a0.x + a1.x; o.y = a0.y + a1.y; o.z = a0.z + a1.z; o.w = a0.w + a1.w;
        ((float4*)g_sumfeat)[(pbase + pl) * 64 + f4] = o;
    }
}

// ---------------------------------------------------------------------------
// K2: per-layer GEMM  h = sumfeat @ W_l   ([4096,256]@[256,128]) with FFMA2.
// Accumulators paired along rows: acc2[i2][j] holds rows {2i2, 2i2+1}, col j.
// ---------------------------------------------------------------------------
__global__ __launch_bounds__(256) void k2_gemm(const float* __restrict__ W) {
    const int l  = blockIdx.y;
    const int bm = blockIdx.x;
    __shared__ float As[32][132];   // transposed A tile (row-pairs contiguous)
    __shared__ float Bs[32][128];

    const int tid = threadIdx.x;
    const int tr = tid >> 4;
    const int tc = tid & 15;

    u64 acc2[4][8];
    #pragma unroll
    for (int i = 0; i < 4; i++)
        #pragma unroll
        for (int j = 0; j < 8; j++) acc2[i][j] = 0ull;

    const float* __restrict__ Wl = W + l * FEAT * EMB;

    for (int k0 = 0; k0 < FEAT; k0 += 32) {
        #pragma unroll
        for (int i = 0; i < 16; i++) {
            const int idx = tid + i * 256;
            const int row = idx >> 5, kk = idx & 31;
            As[kk][row] = g_sumfeat[((bm * 128 + row) * 4 + l) * FEAT + k0 + kk];
        }
        #pragma unroll
        for (int i = 0; i < 16; i++) {
            const int idx = tid + i * 256;
            const int f = idx >> 7, m = idx & 127;
            Bs[f][m] = Wl[(k0 + f) * EMB + m];
        }
        __syncthreads();
        #pragma unroll
        for (int kk = 0; kk < 32; kk++) {
            const u64* a64 = (const u64*)&As[kk][tr * 8];
            u64 a2[4];
            #pragma unroll
            for (int i = 0; i < 4; i++) a2[i] = a64[i];
            const float4 bv0 = *(const float4*)&Bs[kk][tc * 8];
            const float4 bv1 = *(const float4*)&Bs[kk][tc * 8 + 4];
            u64 bb[8];
            bb[0] = pack2(bv0.x); bb[1] = pack2(bv0.y);
            bb[2] = pack2(bv0.z); bb[3] = pack2(bv0.w);
            bb[4] = pack2(bv1.x); bb[5] = pack2(bv1.y);
            bb[6] = pack2(bv1.z); bb[7] = pack2(bv1.w);
            #pragma unroll
            for (int i = 0; i < 4; i++)
                #pragma unroll
                for (int j = 0; j < 8; j++)
                    acc2[i][j] = fma2(a2[i], bb[j], acc2[i][j]);
        }
        __syncthreads();
    }
    #pragma unroll
    for (int i2 = 0; i2 < 4; i2++) {
        float r0v[8], r1v[8];
        #pragma unroll
        for (int j = 0; j < 8; j++) {
            const float2 f2 = unpk(acc2[i2][j]);
            r0v[j] = f2.x; r1v[j] = f2.y;
        }
        const int row0 = bm * 128 + tr * 8 + 2 * i2;
        float4* d0 = (float4*)&g_h[(row0 * 4 + l) * EMB + tc * 8];
        d0[0] = make_float4(r0v[0], r0v[1], r0v[2], r0v[3]);
        d0[1] = make_float4(r0v[4], r0v[5], r0v[6], r0v[7]);
        float4* d1 = (float4*)&g_h[((row0 + 1) * 4 + l) * EMB + tc * 8];
        d1[0] = make_float4(r1v[0], r1v[1], r1v[2], r1v[3]);
        d1[1] = make_float4(r1v[4], r1v[5], r1v[6], r1v[7]);
    }
}

// ---------------------------------------------------------------------------
// K34 (fused): per 128-pair tile (= 32 batch rows x 4 layers):
//   phase1: scores = tanh(H@Ws1).Ws2   (FFMA2 GEMM core)
//   phase2: softmax over layers
//   phase3: agg[32][128] = sum_l att*h
//   phase4: ne = agg @ TW              (staged smem GEMM)
//   phase5: residual + L2 normalize    (warp-local, no barriers)
// ---------------------------------------------------------------------------
__global__ __launch_bounds__(256) void k34_fused(const float* __restrict__ Ws1,
                                                 const float* __restrict__ Ws2,
                                                 const float* __restrict__ TW,
                                                 const float* __restrict__ lemb,
                                                 const int* __restrict__ node_i,
                                                 const int* __restrict__ layers,
                                                 float* __restrict__ out) {
    __shared__ float As[32][132];     // phase1 A tiles; phase3/4: aliased as aggs
    __shared__ float Bs[32][128];     // phase1 Ws1 tiles; phase4 TW tiles
    __shared__ float red[128][16];
    __shared__ float scr[128];
    __shared__ float att[32][4];
    __shared__ float w2s[128];

    const int tid = threadIdx.x;
    const int bm = blockIdx.x;          // 128 blocks
    const int pb = bm * 128;            // global pair base
    const int B0 = bm * 32;             // global batch-row base

    if (tid < 128) w2s[tid] = Ws2[tid];
    const int tr = tid >> 4, tc = tid & 15;

    // ---- phase 1: GEMM H@Ws1 with FFMA2 ----
    u64 acc2[4][8];
    #pragma unroll
    for (int i = 0; i < 4; i++)
        #pragma unroll
        for (int j = 0; j < 8; j++) acc2[i][j] = 0ull;

    for (int k0 = 0; k0 < EMB; k0 += 32) {
        #pragma unroll
        for (int i = 0; i < 16; i++) {
            const int idx = tid + i * 256;
            const int row = idx >> 5, kk = idx & 31;
            As[kk][row] = g_h[(pb + row) * EMB + k0 + kk];
        }
        #pragma unroll
        for (int i = 0; i < 16; i++) {
            const int idx = tid + i * 256;
            const int f = idx >> 7, m = idx & 127;
            Bs[f][m] = Ws1[(k0 + f) * EMB + m];
        }
        __syncthreads();
        #pragma unroll
        for (int kk = 0; kk < 32; kk++) {
            const u64* a64 = (const u64*)&As[kk][tr * 8];
            u64 a2[4];
            #pragma unroll
            for (int i = 0; i < 4; i++) a2[i] = a64[i];
            const float4 bv0 = *(const float4*)&Bs[kk][tc * 8];
            const float4 bv1 = *(const float4*)&Bs[kk][tc * 8 + 4];
            u64 bb[8];
            bb[0] = pack2(bv0.x); bb[1] = pack2(bv0.y);
            bb[2] = pack2(bv0.z); bb[3] = pack2(bv0.w);
            bb[4] = pack2(bv1.x); bb[5] = pack2(bv1.y);
            bb[6] = pack2(bv1.z); bb[7] = pack2(bv1.w);
            #pragma unroll
            for (int i = 0; i < 4; i++)
                #pragma unroll
                for (int j = 0; j < 8; j++)
                    acc2[i][j] = fma2(a2[i], bb[j], acc2[i][j]);
        }
        __syncthreads();
    }
    // epilogue: tanh + dot Ws2, partial per column-thread
    #pragma unroll
    for (int i2 = 0; i2 < 4; i2++) {
        float p0 = 0.f, p1 = 0.f;
        #pragma unroll
        for (int j = 0; j < 8; j++) {
            const float2 f2 = unpk(acc2[i2][j]);
            const float w = w2s[tc * 8 + j];
            p0 = fmaf(tanhf(f2.x), w, p0);
            p1 = fmaf(tanhf(f2.y), w, p1);
        }
        red[tr * 8 + 2 * i2][tc]     = p0;
        red[tr * 8 + 2 * i2 + 1][tc] = p1;
    }
    __syncthreads();
    if (tid < 128) {
        float s = 0.f;
        #pragma unroll
        for (int c = 0; c < 16; c++) s += red[tid][c];
        scr[tid] = s;
    }
    __syncthreads();

    // ---- phase 2: softmax over 4 layers (32 rows) ----
    if (tid < 32) {
        const float s0 = scr[tid * 4 + 0];
        const float s1 = scr[tid * 4 + 1];
        const float s2 = scr[tid * 4 + 2];
        const float s3 = scr[tid * 4 + 3];
        const float mx = fmaxf(fmaxf(s0, s1), fmaxf(s2, s3));
        const float e0 = __expf(s0 - mx), e1 = __expf(s1 - mx);
        const float e2 = __expf(s2 - mx), e3 = __expf(s3 - mx);
        const float inv = 1.f / (e0 + e1 + e2 + e3);
        att[tid][0] = e0 * inv; att[tid][1] = e1 * inv;
        att[tid][2] = e2 * inv; att[tid][3] = e3 * inv;
    }
    __syncthreads();

    // ---- phase 3: attention-weighted aggregation -> aggs (aliases As) ----
    float (*aggs)[132] = (float(*)[132])As;
    {
        const int m = tid & 127;
        const int bh = tid >> 7;            // 0..1
        #pragma unroll
        for (int t = 0; t < 16; t++) {
            const int b = bh * 16 + t;
            const int base = (pb + b * 4) * EMB + m;
            float a = att[b][0] * g_h[base];
            a = fmaf(att[b][1], g_h[base + EMB], a);
            a = fmaf(att[b][2], g_h[base + 2 * EMB], a);
            a = fmaf(att[b][3], g_h[base + 3 * EMB], a);
            aggs[b][m] = a;
        }
    }
    __syncthreads();

    // ---- phase 4: ne = agg @ TW  (32x128 @ 128x128), staged TW tiles ----
    // thread map: wr = tid>>5 (warp, 4 rows each), wc = tid&31 (4 cols each)
    const int wr = tid >> 5;
    const int wc = tid & 31;
    float acc[4][4];
    #pragma unroll
    for (int i = 0; i < 4; i++)
        #pragma unroll
        for (int j = 0; j < 4; j++) acc[i][j] = 0.f;

    for (int kc = 0; kc < 4; kc++) {
        #pragma unroll
        for (int i = 0; i < 16; i++) {
            const int idx = tid + i * 256;
            const int f = idx >> 7, m = idx & 127;
            Bs[f][m] = TW[(kc * 32 + f) * EMB + m];
        }
        __syncthreads();
        #pragma unroll
        for (int kk = 0; kk < 32; kk++) {
            const int k = kc * 32 + kk;
            float a[4];
            #pragma unroll
            for (int i = 0; i < 4; i++) a[i] = aggs[wr * 4 + i][k];
            const float4 bv = *(const float4*)&Bs[kk][wc * 4];
            const float b[4] = {bv.x, bv.y, bv.z, bv.w};
            #pragma unroll
            for (int i = 0; i < 4; i++)
                #pragma unroll
                for (int j = 0; j < 4; j++)
                    acc[i][j] = fmaf(a[i], b[j], acc[i][j]);
        }
        __syncthreads();
    }

    // ---- phase 5: residual + L2 normalize (warp-local) ----
    #pragma unroll
    for (int i = 0; i < 4; i++) {
        const int bg = B0 + wr * 4 + i;
        const int li = node_i[bg] * 4 + layers[bg];
        const float4 lv = *(const float4*)&lemb[li * EMB + wc * 4];
        float f[4];
        f[0] = acc[i][0] + lv.x;
        f[1] = acc[i][1] + lv.y;
        f[2] = acc[i][2] + lv.z;
        f[3] = acc[i][3] + lv.w;
        float v = f[0]*f[0] + f[1]*f[1] + f[2]*f[2] + f[3]*f[3];
        #pragma unroll
        for (int off = 16; off > 0; off >>= 1)
            v += __shfl_xor_sync(0xffffffffu, v, off);
        const float inv = 1.f / fmaxf(sqrtf(v), 1e-12f);
        float4 o;
        o.x = f[0] * inv; o.y = f[1] * inv; o.z = f[2] * inv; o.w = f[3] * inv;
        *(float4*)&out[bg * EMB + wc * 4] = o;
    }
}

// ---------------------------------------------------------------------------
extern "C" void kernel_launch(void* const* d_in, const int* in_sizes, int n_in,
                              void* d_out, int out_size) {
    const int*   layers  = (const int*)d_in[0];
    const int*   node_i  = (const int*)d_in[1];
    const int*   neighs  = (const int*)d_in[2];
    const float* feats   = (const float*)d_in[3];
    const float* lemb    = (const float*)d_in[4];
    const float* net     = (const float*)d_in[5];
    const float* TW      = (const float*)d_in[6];
    const float* Ws1     = (const float*)d_in[7];
    const float* Ws2     = (const float*)d_in[8];
    float* out = (float*)d_out;

    k1_gather<<<PAIRS / 16, 256>>>(neighs, feats);
    k2_gemm<<<dim3(BATCH / 128, LAYERS), 256>>>(net);
    k34_fused<<<PAIRS / 128, 256>>>(Ws1, Ws2, TW, lemb, node_i, layers, out);
}

// round 7
// speedup vs baseline: 1.4403x; 1.0726x over previous
#include <cuda_runtime.h>
#include <cuda_fp16.h>

#define NODE_NUM 100000
#define BATCH 4096
#define LAYERS 4
#define EMB 128
#define FEAT 256
#define NEIGH 32
#define PAIRS (BATCH*LAYERS)   // 16384

typedef unsigned long long u64;

// packed fp32x2 helpers (sm_103a FFMA2 — PTX-only per SASS_QUICKREF)
__device__ __forceinline__ u64 pack2(float x) {
    u64 r; asm("mov.b64 %0,{%1,%1};" : "=l"(r) : "f"(x)); return r;
}
__device__ __forceinline__ u64 fma2(u64 a, u64 b, u64 c) {
    u64 d; asm("fma.rn.f32x2 %0,%1,%2,%3;" : "=l"(d) : "l"(a), "l"(b), "l"(c)); return d;
}
__device__ __forceinline__ float2 unpk(u64 v) {
    float lo, hi; asm("mov.b64 {%0,%1},%2;" : "=f"(lo), "=f"(hi) : "l"(v));
    return make_float2(lo, hi);
}

// Scratch (device globals: allocation-free rule).
// g_featsh is accessed via float4/half2 vectors -> force 16B alignment.
__device__ __align__(16) __half g_featsh[NODE_NUM * FEAT];  // 51.2 MB
__device__ float  g_sumfeat[PAIRS * FEAT];                  // 16 MB
__device__ float  g_h[PAIRS * EMB];                         // 8 MB

// ---------------------------------------------------------------------------
// K0: convert features fp32 -> fp16 (once per launch; DRAM-bound ~12us)
// ---------------------------------------------------------------------------
__global__ __launch_bounds__(256) void k0_convert(const float* __restrict__ feats) {
    const int stride = gridDim.x * blockDim.x;
    const float4* __restrict__ src = (const float4*)feats;
    half2* __restrict__ dst = (half2*)g_featsh;
    const int total4 = NODE_NUM * FEAT / 4;   // 6.4M float4
    for (int k = blockIdx.x * blockDim.x + threadIdx.x; k < total4; k += stride) {
        const float4 v = src[k];
        dst[2 * k]     = __floats2half2_rn(v.x, v.y);
        dst[2 * k + 1] = __floats2half2_rn(v.z, v.w);
    }
}

// ---------------------------------------------------------------------------
// K1: fp16 neighbor gather + sum. Warp per pair; lane j holds neighbor index,
// broadcast via shuffle; each lane loads float4 (8 halves) per neighbor.
// LTS traffic: 256 MB (vs 512 MB fp32), table L2-resident.
// ---------------------------------------------------------------------------
__global__ __launch_bounds__(256) void k1_gather_h(const int* __restrict__ neighs) {
    const int tid  = threadIdx.x;
    const int warp = tid >> 5, lane = tid & 31;
    const int p = blockIdx.x * 8 + warp;              // pair index
    const int myidx = neighs[p * 32 + lane];          // one neighbor per lane
    const float4* __restrict__ base = (const float4*)g_featsh;  // 8 halves/elem

    float acc[8];
    #pragma unroll
    for (int q = 0; q < 8; q++) acc[q] = 0.f;

    #pragma unroll
    for (int j = 0; j < NEIGH; j++) {
        const int n = __shfl_sync(0xffffffffu, myidx, j);
        const float4 v = base[n * 32 + lane];         // row = 32 float4 (512B)
        const half2* h2 = (const half2*)&v;
        #pragma unroll
        for (int q = 0; q < 4; q++) {
            const float2 f = __half22float2(h2[q]);
            acc[2 * q]     += f.x;
            acc[2 * q + 1] += f.y;
        }
    }
    float4* dst = (float4*)&g_sumfeat[p * FEAT + lane * 8];
    dst[0] = make_float4(acc[0], acc[1], acc[2], acc[3]);
    dst[1] = make_float4(acc[4], acc[5], acc[6], acc[7]);
}

// ---------------------------------------------------------------------------
// K2: per-layer GEMM  h = sumfeat @ W_l   ([4096,256]@[256,128]) with FFMA2.
// ---------------------------------------------------------------------------
__global__ __launch_bounds__(256) void k2_gemm(const float* __restrict__ W) {
    const int l  = blockIdx.y;
    const int bm = blockIdx.x;
    __shared__ float As[32][132];
    __shared__ float Bs[32][128];

    const int tid = threadIdx.x;
    const int tr = tid >> 4;
    const int tc = tid & 15;

    u64 acc2[4][8];
    #pragma unroll
    for (int i = 0; i < 4; i++)
        #pragma unroll
        for (int j = 0; j < 8; j++) acc2[i][j] = 0ull;

    const float* __restrict__ Wl = W + l * FEAT * EMB;

    for (int k0 = 0; k0 < FEAT; k0 += 32) {
        #pragma unroll
        for (int i = 0; i < 16; i++) {
            const int idx = tid + i * 256;
            const int row = idx >> 5, kk = idx & 31;
            As[kk][row] = g_sumfeat[((bm * 128 + row) * 4 + l) * FEAT + k0 + kk];
        }
        #pragma unroll
        for (int i = 0; i < 16; i++) {
            const int idx = tid + i * 256;
            const int f = idx >> 7, m = idx & 127;
            Bs[f][m] = Wl[(k0 + f) * EMB + m];
        }
        __syncthreads();
        #pragma unroll
        for (int kk = 0; kk < 32; kk++) {
            const u64* a64 = (const u64*)&As[kk][tr * 8];
            u64 a2[4];
            #pragma unroll
            for (int i = 0; i < 4; i++) a2[i] = a64[i];
            const float4 bv0 = *(const float4*)&Bs[kk][tc * 8];
            const float4 bv1 = *(const float4*)&Bs[kk][tc * 8 + 4];
            u64 bb[8];
            bb[0] = pack2(bv0.x); bb[1] = pack2(bv0.y);
            bb[2] = pack2(bv0.z); bb[3] = pack2(bv0.w);
            bb[4] = pack2(bv1.x); bb[5] = pack2(bv1.y);
            bb[6] = pack2(bv1.z); bb[7] = pack2(bv1.w);
            #pragma unroll
            for (int i = 0; i < 4; i++)
                #pragma unroll
                for (int j = 0; j < 8; j++)
                    acc2[i][j] = fma2(a2[i], bb[j], acc2[i][j]);
        }
        __syncthreads();
    }
    #pragma unroll
    for (int i2 = 0; i2 < 4; i2++) {
        float r0v[8], r1v[8];
        #pragma unroll
        for (int j = 0; j < 8; j++) {
            const float2 f2 = unpk(acc2[i2][j]);
            r0v[j] = f2.x; r1v[j] = f2.y;
        }
        const int row0 = bm * 128 + tr * 8 + 2 * i2;
        float4* d0 = (float4*)&g_h[(row0 * 4 + l) * EMB + tc * 8];
        d0[0] = make_float4(r0v[0], r0v[1], r0v[2], r0v[3]);
        d0[1] = make_float4(r0v[4], r0v[5], r0v[6], r0v[7]);
        float4* d1 = (float4*)&g_h[((row0 + 1) * 4 + l) * EMB + tc * 8];
        d1[0] = make_float4(r1v[0], r1v[1], r1v[2], r1v[3]);
        d1[1] = make_float4(r1v[4], r1v[5], r1v[6], r1v[7]);
    }
}

// ---------------------------------------------------------------------------
// K34 (fused): scores -> softmax -> agg -> agg@TW -> residual+normalize.
// ---------------------------------------------------------------------------
__global__ __launch_bounds__(256) void k34_fused(const float* __restrict__ Ws1,
                                                 const float* __restrict__ Ws2,
                                                 const float* __restrict__ TW,
                                                 const float* __restrict__ lemb,
                                                 const int* __restrict__ node_i,
                                                 const int* __restrict__ layers,
                                                 float* __restrict__ out) {
    __shared__ float As[32][132];
    __shared__ float Bs[32][128];
    __shared__ float red[128][16];
    __shared__ float scr[128];
    __shared__ float att[32][4];
    __shared__ float w2s[128];

    const int tid = threadIdx.x;
    const int bm = blockIdx.x;
    const int pb = bm * 128;
    const int B0 = bm * 32;

    if (tid < 128) w2s[tid] = Ws2[tid];
    const int tr = tid >> 4, tc = tid & 15;

    // ---- phase 1: GEMM H@Ws1 with FFMA2 ----
    u64 acc2[4][8];
    #pragma unroll
    for (int i = 0; i < 4; i++)
        #pragma unroll
        for (int j = 0; j < 8; j++) acc2[i][j] = 0ull;

    for (int k0 = 0; k0 < EMB; k0 += 32) {
        #pragma unroll
        for (int i = 0; i < 16; i++) {
            const int idx = tid + i * 256;
            const int row = idx >> 5, kk = idx & 31;
            As[kk][row] = g_h[(pb + row) * EMB + k0 + kk];
        }
        #pragma unroll
        for (int i = 0; i < 16; i++) {
            const int idx = tid + i * 256;
            const int f = idx >> 7, m = idx & 127;
            Bs[f][m] = Ws1[(k0 + f) * EMB + m];
        }
        __syncthreads();
        #pragma unroll
        for (int kk = 0; kk < 32; kk++) {
            const u64* a64 = (const u64*)&As[kk][tr * 8];
            u64 a2[4];
            #pragma unroll
            for (int i = 0; i < 4; i++) a2[i] = a64[i];
            const float4 bv0 = *(const float4*)&Bs[kk][tc * 8];
            const float4 bv1 = *(const float4*)&Bs[kk][tc * 8 + 4];
            u64 bb[8];
            bb[0] = pack2(bv0.x); bb[1] = pack2(bv0.y);
            bb[2] = pack2(bv0.z); bb[3] = pack2(bv0.w);
            bb[4] = pack2(bv1.x); bb[5] = pack2(bv1.y);
            bb[6] = pack2(bv1.z); bb[7] = pack2(bv1.w);
            #pragma unroll
            for (int i = 0; i < 4; i++)
                #pragma unroll
                for (int j = 0; j < 8; j++)
                    acc2[i][j] = fma2(a2[i], bb[j], acc2[i][j]);
        }
        __syncthreads();
    }
    #pragma unroll
    for (int i2 = 0; i2 < 4; i2++) {
        float p0 = 0.f, p1 = 0.f;
        #pragma unroll
        for (int j = 0; j < 8; j++) {
            const float2 f2 = unpk(acc2[i2][j]);
            const float w = w2s[tc * 8 + j];
            p0 = fmaf(tanhf(f2.x), w, p0);
            p1 = fmaf(tanhf(f2.y), w, p1);
        }
        red[tr * 8 + 2 * i2][tc]     = p0;
        red[tr * 8 + 2 * i2 + 1][tc] = p1;
    }
    __syncthreads();
    if (tid < 128) {
        float s = 0.f;
        #pragma unroll
        for (int c = 0; c < 16; c++) s += red[tid][c];
        scr[tid] = s;
    }
    __syncthreads();

    // ---- phase 2: softmax over 4 layers ----
    if (tid < 32) {
        const float s0 = scr[tid * 4 + 0];
        const float s1 = scr[tid * 4 + 1];
        const float s2 = scr[tid * 4 + 2];
        const float s3 = scr[tid * 4 + 3];
        const float mx = fmaxf(fmaxf(s0, s1), fmaxf(s2, s3));
        const float e0 = __expf(s0 - mx), e1 = __expf(s1 - mx);
        const float e2 = __expf(s2 - mx), e3 = __expf(s3 - mx);
        const float inv = 1.f / (e0 + e1 + e2 + e3);
        att[tid][0] = e0 * inv; att[tid][1] = e1 * inv;
        att[tid][2] = e2 * inv; att[tid][3] = e3 * inv;
    }
    __syncthreads();

    // ---- phase 3: attention-weighted aggregation -> aggs (aliases As) ----
    float (*aggs)[132] = (float(*)[132])As;
    {
        const int m = tid & 127;
        const int bh = tid >> 7;
        #pragma unroll
        for (int t = 0; t < 16; t++) {
            const int b = bh * 16 + t;
            const int base = (pb + b * 4) * EMB + m;
            float a = att[b][0] * g_h[base];
            a = fmaf(att[b][1], g_h[base + EMB], a);
            a = fmaf(att[b][2], g_h[base + 2 * EMB], a);
            a = fmaf(att[b][3], g_h[base + 3 * EMB], a);
            aggs[b][m] = a;
        }
    }
    __syncthreads();

    // ---- phase 4: ne = agg @ TW ----
    const int wr = tid >> 5;
    const int wc = tid & 31;
    float acc[4][4];
    #pragma unroll
    for (int i = 0; i < 4; i++)
        #pragma unroll
        for (int j = 0; j < 4; j++) acc[i][j] = 0.f;

    for (int kc = 0; kc < 4; kc++) {
        #pragma unroll
        for (int i = 0; i < 16; i++) {
            const int idx = tid + i * 256;
            const int f = idx >> 7, m = idx & 127;
            Bs[f][m] = TW[(kc * 32 + f) * EMB + m];
        }
        __syncthreads();
        #pragma unroll
        for (int kk = 0; kk < 32; kk++) {
            const int k = kc * 32 + kk;
            float a[4];
            #pragma unroll
            for (int i = 0; i < 4; i++) a[i] = aggs[wr * 4 + i][k];
            const float4 bv = *(const float4*)&Bs[kk][wc * 4];
            const float b[4] = {bv.x, bv.y, bv.z, bv.w};
            #pragma unroll
            for (int i = 0; i < 4; i++)
                #pragma unroll
                for (int j = 0; j < 4; j++)
                    acc[i][j] = fmaf(a[i], b[j], acc[i][j]);
        }
        __syncthreads();
    }

    // ---- phase 5: residual + L2 normalize (warp-local) ----
    #pragma unroll
    for (int i = 0; i < 4; i++) {
        const int bg = B0 + wr * 4 + i;
        const int li = node_i[bg] * 4 + layers[bg];
        const float4 lv = *(const float4*)&lemb[li * EMB + wc * 4];
        float f[4];
        f[0] = acc[i][0] + lv.x;
        f[1] = acc[i][1] + lv.y;
        f[2] = acc[i][2] + lv.z;
        f[3] = acc[i][3] + lv.w;
        float v = f[0]*f[0] + f[1]*f[1] + f[2]*f[2] + f[3]*f[3];
        #pragma unroll
        for (int off = 16; off > 0; off >>= 1)
            v += __shfl_xor_sync(0xffffffffu, v, off);
        const float inv = 1.f / fmaxf(sqrtf(v), 1e-12f);
        float4 o;
        o.x = f[0] * inv; o.y = f[1] * inv; o.z = f[2] * inv; o.w = f[3] * inv;
        *(float4*)&out[bg * EMB + wc * 4] = o;
    }
}

// ---------------------------------------------------------------------------
extern "C" void kernel_launch(void* const* d_in, const int* in_sizes, int n_in,
                              void* d_out, int out_size) {
    const int*   layers  = (const int*)d_in[0];
    const int*   node_i  = (const int*)d_in[1];
    const int*   neighs  = (const int*)d_in[2];
    const float* feats   = (const float*)d_in[3];
    const float* lemb    = (const float*)d_in[4];
    const float* net     = (const float*)d_in[5];
    const float* TW      = (const float*)d_in[6];
    const float* Ws1     = (const float*)d_in[7];
    const float* Ws2     = (const float*)d_in[8];
    float* out = (float*)d_out;

    k0_convert<<<2048, 256>>>(feats);
    k1_gather_h<<<PAIRS / 8, 256>>>(neighs);
    k2_gemm<<<dim3(BATCH / 128, LAYERS), 256>>>(net);
    k34_fused<<<PAIRS / 128, 256>>>(Ws1, Ws2, TW, lemb, node_i, layers, out);
}